// round 2
// baseline (speedup 1.0000x reference)
#include <cuda_runtime.h>
#include <math.h>

#define TP 98
typedef unsigned long long ull;

__device__ __align__(16) float g_xn[96*96*96];
__device__ __align__(16) float g_M[8*96*96];
__device__ __align__(16) float g_N[8*96*96];
__device__ __align__(16) float g_u[8*96];
__device__ __align__(16) float g_w[8*96];
__device__ __align__(16) float g_cc[8];
__device__ __align__(16) float g_bp[96];
__device__ __align__(16) float g_part[8*96*96*96];
__device__ __align__(16) float g_O[96*96*96];

__device__ __forceinline__ ull pack2(float a) {
    ull r; asm("mov.b64 %0, {%1, %2};" : "=l"(r) : "f"(a), "f"(a)); return r;
}
__device__ __forceinline__ ull fma2(ull a, ull b, ull c) {
    ull d; asm("fma.rn.f32x2 %0, %1, %2, %3;" : "=l"(d) : "l"(a), "l"(b), "l"(c)); return d;
}
__device__ __forceinline__ float2 unpk(ull p) {
    float2 f; asm("mov.b64 {%0, %1}, %2;" : "=f"(f.x), "=f"(f.y) : "l"(p)); return f;
}

// 96x96x96 GEMM microkernel: 256 thr (16x16), 6x6/thread, f32x2 accumulators.
// AMODE 0: A(i,k)=A[k*TP+i] ; AMODE 1: A(i,k)=A[i*96+k]. B pitch = PB.
template<int AMODE, int PB>
__device__ __forceinline__ void gemm96(const float* __restrict__ A,
                                       const float* __restrict__ B,
                                       int i0, int j0, ull acc[6][3]) {
    const float* Bj = B + j0;
#pragma unroll 2
    for (int k = 0; k < 96; k += 2) {
        ull b0[3], b1[3];
#pragma unroll
        for (int p = 0; p < 3; ++p) {
            b0[p] = *(const ull*)(Bj + k * PB + 2 * p);
            b1[p] = *(const ull*)(Bj + (k + 1) * PB + 2 * p);
        }
        ull a0[6], a1[6];
        if (AMODE == 0) {
#pragma unroll
            for (int ii = 0; ii < 3; ++ii) {
                float2 f0 = *(const float2*)(A + k * TP + i0 + 2 * ii);
                float2 f1 = *(const float2*)(A + (k + 1) * TP + i0 + 2 * ii);
                a0[2*ii] = pack2(f0.x); a0[2*ii+1] = pack2(f0.y);
                a1[2*ii] = pack2(f1.x); a1[2*ii+1] = pack2(f1.y);
            }
        } else {
#pragma unroll
            for (int i = 0; i < 6; ++i) {
                float2 f = *(const float2*)(A + (i0 + i) * 96 + k);
                a0[i] = pack2(f.x); a1[i] = pack2(f.y);
            }
        }
#pragma unroll
        for (int i = 0; i < 6; ++i)
#pragma unroll
            for (int p = 0; p < 3; ++p)
                acc[i][p] = fma2(a0[i], b0[p], acc[i][p]);
#pragma unroll
        for (int i = 0; i < 6; ++i)
#pragma unroll
            for (int p = 0; p < 3; ++p)
                acc[i][p] = fma2(a1[i], b1[p], acc[i][p]);
    }
}

// ---- 1) GroupNorm: one block per (b, group); group = 12 ch x 96 = 1152 elems
__global__ void gn_kernel(const float* __restrict__ x,
                          const float* __restrict__ gamma,
                          const float* __restrict__ beta) {
    const int b = blockIdx.x, g = blockIdx.y, tid = threadIdx.x;
    const float* xp = x + b * 9216 + g * 1152;
    float vals[9], sum = 0.f, sq = 0.f;
#pragma unroll
    for (int t = 0; t < 9; ++t) {
        float v = xp[tid + t * 128];
        vals[t] = v; sum += v; sq += v * v;
    }
    __shared__ float s1[128], s2[128];
    s1[tid] = sum; s2[tid] = sq;
    __syncthreads();
    for (int o = 64; o > 0; o >>= 1) {
        if (tid < o) { s1[tid] += s1[tid + o]; s2[tid] += s2[tid + o]; }
        __syncthreads();
    }
    const float mean = s1[0] * (1.f / 1152.f);
    const float var  = s2[0] * (1.f / 1152.f) - mean * mean;
    const float rstd = rsqrtf(var + 1e-5f);
#pragma unroll
    for (int t = 0; t < 9; ++t) {
        int e = tid + t * 128;
        int ch = g * 12 + e / 96;
        g_xn[b * 9216 + g * 1152 + e] = (vals[t] - mean) * rstd * gamma[ch] + beta[ch];
    }
}

// ---- 2) Precompute M, N, u, w, c, b' (one block per head)
__global__ __launch_bounds__(256, 1)
void pre_kernel(const float* __restrict__ Wq, const float* __restrict__ bq,
                const float* __restrict__ Wk, const float* __restrict__ bk,
                const float* __restrict__ Wv, const float* __restrict__ bv,
                const float* __restrict__ Wo, const float* __restrict__ bo) {
    const int h = blockIdx.x, tid = threadIdx.x;
    extern __shared__ float sm[];
    float* wq  = sm;
    float* wkT = sm + 9216;
    float* wv  = wkT + 96 * TP;
    float* wo  = wv + 9216;
    for (int idx = tid; idx < 9216; idx += 256) {
        int i = idx / 96, d = idx % 96;
        wq[idx]         = Wq[i * 768 + h * 96 + d];
        wkT[d * TP + i] = Wk[i * 768 + h * 96 + d];
        wv[idx]         = Wv[i * 768 + h * 96 + d];
        wo[idx]         = Wo[h * 9216 + idx];
    }
    __syncthreads();
    const float inv = rsqrtf(96.0f);
    const int tx = tid & 15, ty = tid >> 4;
    const int i0 = ty * 6, j0 = tx * 6;
    {
        ull acc[6][3];
#pragma unroll
        for (int i = 0; i < 6; ++i) for (int p = 0; p < 3; ++p) acc[i][p] = 0ULL;
        gemm96<1, TP>(wq, wkT, i0, j0, acc);   // M = Wq_h Wk_h^T
#pragma unroll
        for (int i = 0; i < 6; ++i)
#pragma unroll
            for (int p = 0; p < 3; ++p) {
                float2 f = unpk(acc[i][p]);
                g_M[h * 9216 + (i0 + i) * 96 + j0 + 2 * p]     = f.x * inv;
                g_M[h * 9216 + (i0 + i) * 96 + j0 + 2 * p + 1] = f.y * inv;
            }
    }
    {
        ull acc[6][3];
#pragma unroll
        for (int i = 0; i < 6; ++i) for (int p = 0; p < 3; ++p) acc[i][p] = 0ULL;
        gemm96<1, 96>(wv, wo, i0, j0, acc);    // N = Wv_h Wo_h
#pragma unroll
        for (int i = 0; i < 6; ++i)
#pragma unroll
            for (int p = 0; p < 3; ++p)
                *(ull*)(g_N + h * 9216 + (i0 + i) * 96 + j0 + 2 * p) = acc[i][p];
    }
    if (tid < 96) {
        float a = 0.f, c = 0.f;
        for (int d = 0; d < 96; ++d) {
            a += wq[tid * 96 + d] * bk[h * 96 + d];
            c += wkT[d * TP + tid] * bq[h * 96 + d];
        }
        g_u[h * 96 + tid] = a * inv;
        g_w[h * 96 + tid] = c * inv;
    }
    if (tid == 0) {
        float cs = 0.f;
        for (int d = 0; d < 96; ++d) cs += bq[h * 96 + d] * bk[h * 96 + d];
        g_cc[h] = cs * inv;
    }
    if (h == 0 && tid < 96) {
        float s = bo[tid];
        for (int j = 0; j < 768; ++j) s += bv[j] * Wo[j * 96 + tid];
        g_bp[tid] = s;
    }
}

// ---- 3) Attention per (b,h): X1=tM; S=X1 t^T + rank-1 terms; softmax; X2=tN; P*X2
__global__ __launch_bounds__(256, 1)
void attn_kernel() {
    const int b = blockIdx.x, h = blockIdx.y;
    extern __shared__ float sm[];
    float* tT = sm;                 // 96 x TP (tT[c*TP+s] = t[s][c])
    float* Wb = sm + 96 * TP;       // M, later N
    float* Yb = Wb + 9216;          // X1, later X2
    float* Pb = Yb + 9216;          // softmax P
    float* rv = Pb + 9216;
    float* zv = rv + 96;
    float* uv = zv + 96;
    float* wv = uv + 96;
    const int tid = threadIdx.x;
    const int tx = tid & 15, ty = tid >> 4;
    const int i0 = ty * 6, j0 = tx * 6;
    const float NEGINF = __int_as_float(0xff800000);

    {
        const float* xb = g_xn + b * 9216;
        for (int idx = tid; idx < 9216; idx += 256) {
            int s = idx / 96, c = idx % 96;
            tT[c * TP + s] = xb[idx];
            Wb[idx] = g_M[h * 9216 + idx];
        }
        if (tid < 96) { uv[tid] = g_u[h * 96 + tid]; wv[tid] = g_w[h * 96 + tid]; }
    }
    __syncthreads();

    if (tid < 96) {
        float a = 0.f;
        for (int c = 0; c < 96; ++c) a += tT[c * TP + tid] * uv[c];
        rv[tid] = a;
    } else if (tid < 192) {
        const int j = tid - 96;
        float a = 0.f;
        for (int c = 0; c < 96; ++c) a += tT[c * TP + j] * wv[c];
        zv[j] = a;
    }
    {
        ull acc[6][3];
#pragma unroll
        for (int i = 0; i < 6; ++i) for (int p = 0; p < 3; ++p) acc[i][p] = 0ULL;
        gemm96<0, 96>(tT, Wb, i0, j0, acc);      // X1 = t * M
#pragma unroll
        for (int i = 0; i < 6; ++i)
#pragma unroll
            for (int p = 0; p < 3; ++p)
                *(ull*)(Yb + (i0 + i) * 96 + j0 + 2 * p) = acc[i][p];
    }
    __syncthreads();

    for (int idx = tid; idx < 9216; idx += 256) Wb[idx] = g_N[h * 9216 + idx];
    {
        const float cc = g_cc[h];
        ull acc[6][3];
#pragma unroll
        for (int i = 0; i < 6; ++i) for (int p = 0; p < 3; ++p) acc[i][p] = 0ULL;
        gemm96<1, TP>(Yb, tT, i0, j0, acc);      // S = X1 * t^T
        float sv[6][6];
#pragma unroll
        for (int i = 0; i < 6; ++i)
#pragma unroll
            for (int p = 0; p < 3; ++p) {
                float2 f = unpk(acc[i][p]);
                sv[i][2 * p] = f.x; sv[i][2 * p + 1] = f.y;
            }
#pragma unroll
        for (int i = 0; i < 6; ++i) {
            const int ig = i0 + i;
            const float ri = rv[ig] + cc;
            float m = NEGINF;
#pragma unroll
            for (int j = 0; j < 6; ++j) {
                const int jg = j0 + j;
                float v = sv[i][j] + ri + zv[jg];
                v = (jg <= ig) ? v : NEGINF;
                sv[i][j] = v;
                m = fmaxf(m, v);
            }
#pragma unroll
            for (int d = 1; d < 16; d <<= 1)
                m = fmaxf(m, __shfl_xor_sync(0xffffffffu, m, d));
            float s = 0.f;
#pragma unroll
            for (int j = 0; j < 6; ++j) {
                float e = __expf(sv[i][j] - m);
                sv[i][j] = e; s += e;
            }
#pragma unroll
            for (int d = 1; d < 16; d <<= 1)
                s += __shfl_xor_sync(0xffffffffu, s, d);
            const float is = 1.0f / s;
#pragma unroll
            for (int j = 0; j < 6; ++j)
                Pb[ig * 96 + j0 + j] = sv[i][j] * is;
        }
    }
    __syncthreads();

    {
        ull acc[6][3];
#pragma unroll
        for (int i = 0; i < 6; ++i) for (int p = 0; p < 3; ++p) acc[i][p] = 0ULL;
        gemm96<0, 96>(tT, Wb, i0, j0, acc);      // X2 = t * N
#pragma unroll
        for (int i = 0; i < 6; ++i)
#pragma unroll
            for (int p = 0; p < 3; ++p)
                *(ull*)(Yb + (i0 + i) * 96 + j0 + 2 * p) = acc[i][p];
    }
    __syncthreads();

    {
        ull acc[6][3];
#pragma unroll
        for (int i = 0; i < 6; ++i) for (int p = 0; p < 3; ++p) acc[i][p] = 0ULL;
        gemm96<1, 96>(Pb, Yb, i0, j0, acc);      // AV = P * X2
        float* dst = g_part + (h * 96 + b) * 9216;
#pragma unroll
        for (int i = 0; i < 6; ++i)
#pragma unroll
            for (int p = 0; p < 3; ++p)
                *(ull*)(dst + (i0 + i) * 96 + j0 + 2 * p) = acc[i][p];
    }
}

// ---- 4) Head reduction + bias
__global__ void reduce_kernel() {
    const int idx = blockIdx.x * 256 + threadIdx.x;      // float4 idx, 221184 total
    float4 a = ((const float4*)g_bp)[idx % 24];
#pragma unroll
    for (int h = 0; h < 8; ++h) {
        float4 p = ((const float4*)g_part)[h * 221184 + idx];
        a.x += p.x; a.y += p.y; a.z += p.z; a.w += p.w;
    }
    ((float4*)g_O)[idx] = a;
}

// ---- 5) Broadcast residual add: out[i,j,k,l] = O[j,k,l] + xn[i,j,l]
__global__ void bcast_kernel(float* __restrict__ out) {
    __shared__ float xn_s[16 * 96];
    __shared__ float O_s[16 * 96];
    const int bt = blockIdx.x, st = blockIdx.y, c = blockIdx.z;
    const int tid = threadIdx.x;
    for (int e = tid; e < 1536; e += 256) {
        int r = e / 96, col = e % 96;
        xn_s[e] = g_xn[(size_t)(bt * 16 + r) * 9216 + c * 96 + col];
        O_s[e]  = g_O[(size_t)c * 9216 + (st * 16 + r) * 96 + col];
    }
    __syncthreads();
    const float4* O4 = (const float4*)O_s;
    const float4* X4 = (const float4*)xn_s;
    for (int e = tid; e < 6144; e += 256) {
        int q   = e % 24;
        int s_i = (e / 24) % 16;
        int b_i = e / 384;
        float4 o  = O4[s_i * 24 + q];
        float4 xv = X4[b_i * 24 + q];
        float4 v  = make_float4(o.x + xv.x, o.y + xv.y, o.z + xv.z, o.w + xv.w);
        size_t off = ((size_t)(bt * 16 + b_i) * 96 + (size_t)c) * 9216
                   + (size_t)(st * 16 + s_i) * 96 + (size_t)q * 4;
        __stcs((float4*)(out + off), v);
    }
}

extern "C" void kernel_launch(void* const* d_in, const int* in_sizes, int n_in,
                              void* d_out, int out_size) {
    const float* x     = (const float*)d_in[0];
    const float* Wq    = (const float*)d_in[1];
    const float* bq    = (const float*)d_in[2];
    const float* Wk    = (const float*)d_in[3];
    const float* bk    = (const float*)d_in[4];
    const float* Wv    = (const float*)d_in[5];
    const float* bv    = (const float*)d_in[6];
    const float* Wo    = (const float*)d_in[7];
    const float* bo    = (const float*)d_in[8];
    const float* gamma = (const float*)d_in[9];
    const float* beta  = (const float*)d_in[10];
    float* out = (float*)d_out;

    const int pre_smem  = (9216 * 3 + 96 * TP) * 4;
    const int attn_smem = (96 * TP + 9216 * 3 + 4 * 96) * 4;
    cudaFuncSetAttribute(pre_kernel,  cudaFuncAttributeMaxDynamicSharedMemorySize, pre_smem);
    cudaFuncSetAttribute(attn_kernel, cudaFuncAttributeMaxDynamicSharedMemorySize, attn_smem);

    gn_kernel<<<dim3(96, 8), 128>>>(x, gamma, beta);
    pre_kernel<<<8, 256, pre_smem>>>(Wq, bq, Wk, bk, Wv, bv, Wo, bo);
    attn_kernel<<<dim3(96, 8), 256, attn_smem>>>();
    reduce_kernel<<<864, 256>>>();
    bcast_kernel<<<dim3(6, 6, 96), 256>>>(out);
}

// round 3
// speedup vs baseline: 1.1308x; 1.1308x over previous
#include <cuda_runtime.h>
#include <math.h>

#define TP 98
typedef unsigned long long ull;

__device__ __align__(16) float g_xn[96*96*96];
__device__ __align__(16) float g_M[8*96*96];
__device__ __align__(16) float g_N[8*96*96];
__device__ __align__(16) float g_u[8*96];
__device__ __align__(16) float g_w[8*96];
__device__ __align__(16) float g_cc[8];
__device__ __align__(16) float g_bp[96];
__device__ __align__(16) float g_part[8*96*96*96];
__device__ __align__(16) float g_O[96*96*96];

__device__ __forceinline__ ull pack2(float a) {
    ull r; asm("mov.b64 %0, {%1, %2};" : "=l"(r) : "f"(a), "f"(a)); return r;
}
__device__ __forceinline__ ull pk2(float a, float b) {
    ull r; asm("mov.b64 %0, {%1, %2};" : "=l"(r) : "f"(a), "f"(b)); return r;
}
__device__ __forceinline__ ull fma2(ull a, ull b, ull c) {
    ull d; asm("fma.rn.f32x2 %0, %1, %2, %3;" : "=l"(d) : "l"(a), "l"(b), "l"(c)); return d;
}
__device__ __forceinline__ float2 unpk(ull p) {
    float2 f; asm("mov.b64 {%0, %1}, %2;" : "=f"(f.x), "=f"(f.y) : "l"(p)); return f;
}

// 96x96x96 GEMM microkernel: 256 thr (16x16), 6x6/thread, f32x2 accumulators.
// AMODE 0: A(i,k)=A[k*TP+i] ; AMODE 1: A(i,k)=A[i*96+k]. B pitch = PB.
template<int AMODE, int PB>
__device__ __forceinline__ void gemm96(const float* __restrict__ A,
                                       const float* __restrict__ B,
                                       int i0, int j0, ull acc[6][3]) {
    const float* Bj = B + j0;
#pragma unroll 2
    for (int k = 0; k < 96; k += 2) {
        ull b0[3], b1[3];
#pragma unroll
        for (int p = 0; p < 3; ++p) {
            b0[p] = *(const ull*)(Bj + k * PB + 2 * p);
            b1[p] = *(const ull*)(Bj + (k + 1) * PB + 2 * p);
        }
        ull a0[6], a1[6];
        if (AMODE == 0) {
#pragma unroll
            for (int ii = 0; ii < 3; ++ii) {
                float2 f0 = *(const float2*)(A + k * TP + i0 + 2 * ii);
                float2 f1 = *(const float2*)(A + (k + 1) * TP + i0 + 2 * ii);
                a0[2*ii] = pack2(f0.x); a0[2*ii+1] = pack2(f0.y);
                a1[2*ii] = pack2(f1.x); a1[2*ii+1] = pack2(f1.y);
            }
        } else {
#pragma unroll
            for (int i = 0; i < 6; ++i) {
                float2 f = *(const float2*)(A + (i0 + i) * 96 + k);
                a0[i] = pack2(f.x); a1[i] = pack2(f.y);
            }
        }
#pragma unroll
        for (int i = 0; i < 6; ++i)
#pragma unroll
            for (int p = 0; p < 3; ++p)
                acc[i][p] = fma2(a0[i], b0[p], acc[i][p]);
#pragma unroll
        for (int i = 0; i < 6; ++i)
#pragma unroll
            for (int p = 0; p < 3; ++p)
                acc[i][p] = fma2(a1[i], b1[p], acc[i][p]);
    }
}

// ---- 1) GroupNorm
__global__ void gn_kernel(const float* __restrict__ x,
                          const float* __restrict__ gamma,
                          const float* __restrict__ beta) {
    const int b = blockIdx.x, g = blockIdx.y, tid = threadIdx.x;
    const float* xp = x + b * 9216 + g * 1152;
    float vals[9], sum = 0.f, sq = 0.f;
#pragma unroll
    for (int t = 0; t < 9; ++t) {
        float v = xp[tid + t * 128];
        vals[t] = v; sum += v; sq += v * v;
    }
    __shared__ float s1[128], s2[128];
    s1[tid] = sum; s2[tid] = sq;
    __syncthreads();
    for (int o = 64; o > 0; o >>= 1) {
        if (tid < o) { s1[tid] += s1[tid + o]; s2[tid] += s2[tid + o]; }
        __syncthreads();
    }
    const float mean = s1[0] * (1.f / 1152.f);
    const float var  = s2[0] * (1.f / 1152.f) - mean * mean;
    const float rstd = rsqrtf(var + 1e-5f);
#pragma unroll
    for (int t = 0; t < 9; ++t) {
        int e = tid + t * 128;
        int ch = g * 12 + e / 96;
        g_xn[b * 9216 + g * 1152 + e] = (vals[t] - mean) * rstd * gamma[ch] + beta[ch];
    }
}

// ---- 2) Precompute. grid (8 heads, 2): y=0 -> M,u,w,c,(b'); y=1 -> N
__global__ __launch_bounds__(256, 1)
void pre_kernel(const float* __restrict__ Wq, const float* __restrict__ bq,
                const float* __restrict__ Wk, const float* __restrict__ bk,
                const float* __restrict__ Wv, const float* __restrict__ bv,
                const float* __restrict__ Wo, const float* __restrict__ bo) {
    const int h = blockIdx.x, m = blockIdx.y, tid = threadIdx.x;
    extern __shared__ float sm[];
    float* bufA = sm;           // 9216
    float* bufB = sm + 9216;    // 9408 (pitch TP when transposed)
    const float inv = rsqrtf(96.0f);
    const int tx = tid & 15, ty = tid >> 4;
    const int i0 = ty * 6, j0 = tx * 6;

    if (m == 0) {
        for (int idx = tid; idx < 9216; idx += 256) {
            int i = idx / 96, d = idx % 96;
            bufA[idx]         = Wq[i * 768 + h * 96 + d];
            bufB[d * TP + i]  = Wk[i * 768 + h * 96 + d];
        }
        __syncthreads();
        ull acc[6][3];
#pragma unroll
        for (int i = 0; i < 6; ++i) for (int p = 0; p < 3; ++p) acc[i][p] = 0ULL;
        gemm96<1, TP>(bufA, bufB, i0, j0, acc);   // M = Wq_h Wk_h^T
#pragma unroll
        for (int i = 0; i < 6; ++i)
#pragma unroll
            for (int p = 0; p < 3; ++p) {
                float2 f = unpk(acc[i][p]);
                g_M[h * 9216 + (i0 + i) * 96 + j0 + 2 * p]     = f.x * inv;
                g_M[h * 9216 + (i0 + i) * 96 + j0 + 2 * p + 1] = f.y * inv;
            }
        if (tid < 96) {
            float a = 0.f, c = 0.f;
            for (int d = 0; d < 96; ++d) {
                a += bufA[tid * 96 + d] * bk[h * 96 + d];
                c += bufB[d * TP + tid] * bq[h * 96 + d];
            }
            g_u[h * 96 + tid] = a * inv;
            g_w[h * 96 + tid] = c * inv;
        }
        if (tid == 0) {
            float cs = 0.f;
            for (int d = 0; d < 96; ++d) cs += bq[h * 96 + d] * bk[h * 96 + d];
            g_cc[h] = cs * inv;
        }
        if (h == 0 && tid >= 128 && tid < 224) {
            int c = tid - 128;
            float s = bo[c];
            for (int j = 0; j < 768; ++j) s += bv[j] * Wo[j * 96 + c];
            g_bp[c] = s;
        }
    } else {
        for (int idx = tid; idx < 9216; idx += 256) {
            int i = idx / 96, d = idx % 96;
            bufA[idx] = Wv[i * 768 + h * 96 + d];
            bufB[idx] = Wo[h * 9216 + idx];
        }
        __syncthreads();
        ull acc[6][3];
#pragma unroll
        for (int i = 0; i < 6; ++i) for (int p = 0; p < 3; ++p) acc[i][p] = 0ULL;
        gemm96<1, 96>(bufA, bufB, i0, j0, acc);   // N = Wv_h Wo_h
#pragma unroll
        for (int i = 0; i < 6; ++i)
#pragma unroll
            for (int p = 0; p < 3; ++p)
                *(ull*)(g_N + h * 9216 + (i0 + i) * 96 + j0 + 2 * p) = acc[i][p];
    }
}

// ---- 3) Attention per (b,h), occ=2 via 3-buffer schedule
__global__ __launch_bounds__(256, 2)
void attn_kernel() {
    const int b = blockIdx.x, h = blockIdx.y;
    extern __shared__ float sm[];
    float* tT = sm;                 // 96 x TP ; later reused for X2 (pitch 96)
    float* Wb = sm + 96 * TP;       // M, later N
    float* Yb = Wb + 9216;          // X1, later P
    float* rv = Yb + 9216;
    float* zv = rv + 96;
    float* uv = zv + 96;
    float* wv = uv + 96;
    const int tid = threadIdx.x;
    const int tx = tid & 15, ty = tid >> 4;
    const int i0 = ty * 6, j0 = tx * 6;
    const float NEGINF = __int_as_float(0xff800000);

    {
        const float* xb = g_xn + b * 9216;
        for (int idx = tid; idx < 9216; idx += 256) {
            int s = idx / 96, c = idx % 96;
            tT[c * TP + s] = xb[idx];
            Wb[idx] = g_M[h * 9216 + idx];
        }
        if (tid < 96) { uv[tid] = g_u[h * 96 + tid]; wv[tid] = g_w[h * 96 + tid]; }
    }
    __syncthreads();

    // r/z vectors (half the threads) overlapping with GEMM1 on the rest
    if (tid < 96) {
        float a = 0.f;
        for (int c = 0; c < 96; ++c) a += tT[c * TP + tid] * uv[c];
        rv[tid] = a;
    } else if (tid < 192) {
        const int j = tid - 96;
        float a = 0.f;
        for (int c = 0; c < 96; ++c) a += tT[c * TP + j] * wv[c];
        zv[j] = a;
    }
    {
        ull acc[6][3];
#pragma unroll
        for (int i = 0; i < 6; ++i) for (int p = 0; p < 3; ++p) acc[i][p] = 0ULL;
        gemm96<0, 96>(tT, Wb, i0, j0, acc);        // X1 = t * M
#pragma unroll
        for (int i = 0; i < 6; ++i)
#pragma unroll
            for (int p = 0; p < 3; ++p)
                *(ull*)(Yb + (i0 + i) * 96 + j0 + 2 * p) = acc[i][p];
    }
    __syncthreads();   // X1 visible; M dead

    // N copy (overwrites M) + GEMM2 S = X1 * t^T, softmax kept in regs
    for (int idx = tid; idx < 9216; idx += 256) Wb[idx] = g_N[h * 9216 + idx];
    float sv[6][6];
    {
        const float cc = g_cc[h];
        ull acc[6][3];
#pragma unroll
        for (int i = 0; i < 6; ++i) for (int p = 0; p < 3; ++p) acc[i][p] = 0ULL;
        gemm96<1, TP>(Yb, tT, i0, j0, acc);        // S = X1 * t^T
#pragma unroll
        for (int i = 0; i < 6; ++i)
#pragma unroll
            for (int p = 0; p < 3; ++p) {
                float2 f = unpk(acc[i][p]);
                sv[i][2 * p] = f.x; sv[i][2 * p + 1] = f.y;
            }
#pragma unroll
        for (int i = 0; i < 6; ++i) {
            const int ig = i0 + i;
            const float ri = rv[ig] + cc;
            float mx = NEGINF;
#pragma unroll
            for (int j = 0; j < 6; ++j) {
                const int jg = j0 + j;
                float v = sv[i][j] + ri + zv[jg];
                v = (jg <= ig) ? v : NEGINF;
                sv[i][j] = v;
                mx = fmaxf(mx, v);
            }
#pragma unroll
            for (int d = 1; d < 16; d <<= 1)
                mx = fmaxf(mx, __shfl_xor_sync(0xffffffffu, mx, d));
            float s = 0.f;
#pragma unroll
            for (int j = 0; j < 6; ++j) {
                float e = __expf(sv[i][j] - mx);
                sv[i][j] = e; s += e;
            }
#pragma unroll
            for (int d = 1; d < 16; d <<= 1)
                s += __shfl_xor_sync(0xffffffffu, s, d);
            const float is = 1.0f / s;
#pragma unroll
            for (int j = 0; j < 6; ++j) sv[i][j] *= is;
        }
    }
    __syncthreads();   // all reads of X1 (Yb) done; N copy complete

    // Store P into Yb (X1 slot), then GEMM3 X2 = t * N into registers
    {
#pragma unroll
        for (int i = 0; i < 6; ++i)
#pragma unroll
            for (int p = 0; p < 3; ++p)
                *(ull*)(Yb + (i0 + i) * 96 + j0 + 2 * p) = pk2(sv[i][2*p], sv[i][2*p+1]);
        ull acc[6][3];
#pragma unroll
        for (int i = 0; i < 6; ++i) for (int p = 0; p < 3; ++p) acc[i][p] = 0ULL;
        gemm96<0, 96>(tT, Wb, i0, j0, acc);        // X2 = t * N (in regs)
        __syncthreads();   // tT reads done everywhere; P stores done
#pragma unroll
        for (int i = 0; i < 6; ++i)
#pragma unroll
            for (int p = 0; p < 3; ++p)
                *(ull*)(tT + (i0 + i) * 96 + j0 + 2 * p) = acc[i][p];  // X2 -> tT slot
    }
    __syncthreads();

    // GEMM4: AV = P * X2
    {
        ull acc[6][3];
#pragma unroll
        for (int i = 0; i < 6; ++i) for (int p = 0; p < 3; ++p) acc[i][p] = 0ULL;
        gemm96<1, 96>(Yb, tT, i0, j0, acc);
        float* dst = g_part + (h * 96 + b) * 9216;
#pragma unroll
        for (int i = 0; i < 6; ++i)
#pragma unroll
            for (int p = 0; p < 3; ++p)
                *(ull*)(dst + (i0 + i) * 96 + j0 + 2 * p) = acc[i][p];
    }
}

// ---- 4) Head reduction + bias
__global__ void reduce_kernel() {
    const int idx = blockIdx.x * 256 + threadIdx.x;
    float4 a = ((const float4*)g_bp)[idx % 24];
#pragma unroll
    for (int h = 0; h < 8; ++h) {
        float4 p = ((const float4*)g_part)[h * 221184 + idx];
        a.x += p.x; a.y += p.y; a.z += p.z; a.w += p.w;
    }
    ((float4*)g_O)[idx] = a;
}

// ---- 5) Broadcast residual add: out[i,j,k,l] = O[j,k,l] + xn[i,j,l]
__global__ void bcast_kernel(float* __restrict__ out) {
    __shared__ float xn_s[16 * 96];
    __shared__ float O_s[16 * 96];
    const int bt = blockIdx.x, st = blockIdx.y, c = blockIdx.z;
    const int tid = threadIdx.x;
    for (int e = tid; e < 1536; e += 256) {
        int r = e / 96, col = e % 96;
        xn_s[e] = g_xn[(size_t)(bt * 16 + r) * 9216 + c * 96 + col];
        O_s[e]  = g_O[(size_t)c * 9216 + (st * 16 + r) * 96 + col];
    }
    __syncthreads();
    const float4* O4 = (const float4*)O_s;
    const float4* X4 = (const float4*)xn_s;
    for (int e = tid; e < 6144; e += 256) {
        int q   = e % 24;
        int s_i = (e / 24) % 16;
        int b_i = e / 384;
        float4 o  = O4[s_i * 24 + q];
        float4 xv = X4[b_i * 24 + q];
        float4 v  = make_float4(o.x + xv.x, o.y + xv.y, o.z + xv.z, o.w + xv.w);
        size_t off = ((size_t)(bt * 16 + b_i) * 96 + (size_t)c) * 9216
                   + (size_t)(st * 16 + s_i) * 96 + (size_t)q * 4;
        __stcs((float4*)(out + off), v);
    }
}

extern "C" void kernel_launch(void* const* d_in, const int* in_sizes, int n_in,
                              void* d_out, int out_size) {
    const float* x     = (const float*)d_in[0];
    const float* Wq    = (const float*)d_in[1];
    const float* bq    = (const float*)d_in[2];
    const float* Wk    = (const float*)d_in[3];
    const float* bk    = (const float*)d_in[4];
    const float* Wv    = (const float*)d_in[5];
    const float* bv    = (const float*)d_in[6];
    const float* Wo    = (const float*)d_in[7];
    const float* bo    = (const float*)d_in[8];
    const float* gamma = (const float*)d_in[9];
    const float* beta  = (const float*)d_in[10];
    float* out = (float*)d_out;

    const int pre_smem  = (9216 + 96 * TP) * 4;
    const int attn_smem = (96 * TP + 9216 * 2 + 4 * 96) * 4;   // 112,896 B
    cudaFuncSetAttribute(pre_kernel,  cudaFuncAttributeMaxDynamicSharedMemorySize, pre_smem);
    cudaFuncSetAttribute(attn_kernel, cudaFuncAttributeMaxDynamicSharedMemorySize, attn_smem);

    gn_kernel<<<dim3(96, 8), 128>>>(x, gamma, beta);
    pre_kernel<<<dim3(8, 2), 256, pre_smem>>>(Wq, bq, Wk, bk, Wv, bv, Wo, bo);
    attn_kernel<<<dim3(96, 8), 256, attn_smem>>>();
    reduce_kernel<<<864, 256>>>();
    bcast_kernel<<<dim3(6, 6, 96), 256>>>(out);
}